// round 1
// baseline (speedup 1.0000x reference)
#include <cuda_runtime.h>
#include <math.h>

// Problem constants
#define B_   32
#define C_   64
#define H_   64
#define W_   64
#define K_   128
#define OH_  62
#define OW_  62
#define KHW  9          // 3x3
#define WSZ  576        // C_*KHW per output channel
#define NLOC (OH_*OW_)  // 3844 locations per batch
#define Y_ELEMS ((size_t)B_*K_*OH_*OW_)   // 15,745,024
#define U_ELEMS ((size_t)K_*WSZ)          // 73,728

// Scratch (no cudaMalloc allowed)
__device__ float g_wnorm[K_*WSZ];                 // normalized weights
__device__ int   g_winners[B_*NLOC];              // argmax channel per location
__device__ float g_part[(size_t)B_*K_*WSZ];       // per-batch hebb partials

// ---------------------------------------------------------------------------
// Kernel 1: weight normalization. One block per output channel k.
// ---------------------------------------------------------------------------
__global__ void norm_kernel(const float* __restrict__ weight) {
    __shared__ float red[256];
    __shared__ float s_inv;
    int k = blockIdx.x;
    int tid = threadIdx.x;
    const float* wk = weight + (size_t)k * WSZ;

    float s = 0.f;
    for (int e = tid; e < WSZ; e += 256) {
        float v = wk[e];
        s += v * v;
    }
    red[tid] = s;
    __syncthreads();
    for (int off = 128; off > 0; off >>= 1) {
        if (tid < off) red[tid] += red[tid + off];
        __syncthreads();
    }
    if (tid == 0) {
        float nrm = sqrtf(red[0]);
        if (nrm == 0.f) nrm = 1.f;
        s_inv = nrm;            // store norm, divide per-element (IEEE div, matches ref)
    }
    __syncthreads();
    float nrm = s_inv;
    for (int e = tid; e < WSZ; e += 256) {
        g_wnorm[(size_t)k * WSZ + e] = wk[e] / nrm;
    }
}

// ---------------------------------------------------------------------------
// Kernel 2: direct conv + bias + argmax.
// Grid: (B_, OH_). Block: 512 threads = 64 ow-slots x 8 k-groups.
// Each thread accumulates 16 output channels for one ow.
// Dynamic smem: x slab [64c][3r][64w] (padded) + weight chunk [16c][128k][12].
// ---------------------------------------------------------------------------
#define CONV_THREADS 512
#define XS_PAD  12416                 // 12288 + pad so ow=63 ghost reads stay in-bounds
#define WC_SIZE (16*128*12)           // 24576 floats
#define CONV_SMEM_BYTES ((XS_PAD + WC_SIZE) * 4)

__global__ __launch_bounds__(CONV_THREADS, 1)
void conv_argmax_kernel(const float* __restrict__ x,
                        const float* __restrict__ bias,
                        float* __restrict__ y) {
    extern __shared__ float smem[];
    float* xs = smem;              // [c*192 + i*64 + w]
    float* wc = smem + XS_PAD;     // [(cl*128 + k)*12 + i*4 + j]

    __shared__ float rv[8][64];
    __shared__ int   ri[8][64];

    int b  = blockIdx.x;
    int oh = blockIdx.y;
    int tid = threadIdx.x;
    int ow = tid & 63;
    int kg = tid >> 6;             // 0..7 -> channels [kg*16, kg*16+16)

    // Load input slab: rows oh..oh+2 of all 64 channels (coalesced)
    const float* xb = x + (size_t)b * C_ * H_ * W_;
    for (int l = tid; l < C_ * 3 * W_; l += CONV_THREADS) {
        int c = l / 192;
        int rem = l - c * 192;
        int i = rem >> 6;
        int w = rem & 63;
        xs[l] = xb[(size_t)c * H_ * W_ + (oh + i) * W_ + w];
    }

    float acc[16];
#pragma unroll
    for (int kk = 0; kk < 16; kk++) acc[kk] = 0.f;

    for (int cc = 0; cc < 4; cc++) {
        __syncthreads();
        int base_c = cc * 16;
        // Load weight chunk: 16 input channels x 128 k x 9 taps (padded to 12)
        for (int l = tid; l < 16 * 128 * KHW; l += CONV_THREADS) {
            int cl = l / (128 * KHW);
            int rem = l - cl * (128 * KHW);
            int k = rem / KHW;
            int u = rem - k * KHW;        // i*3+j
            int i = u / 3, j = u - i * 3;
            wc[(cl * 128 + k) * 12 + i * 4 + j] =
                g_wnorm[(size_t)k * WSZ + (base_c + cl) * KHW + u];
        }
        __syncthreads();

        for (int cl = 0; cl < 16; cl++) {
            const float* xrow = xs + (base_c + cl) * 192;
#pragma unroll
            for (int i = 0; i < 3; i++) {
                float xv0 = xrow[i * 64 + ow];
                float xv1 = xrow[i * 64 + ow + 1];
                float xv2 = xrow[i * 64 + ow + 2];
                const float* wbase = wc + (cl * 128 + kg * 16) * 12 + i * 4;
#pragma unroll
                for (int kk = 0; kk < 16; kk++) {
                    float4 wv = *(const float4*)(wbase + kk * 12);
                    acc[kk] = fmaf(xv0, wv.x, acc[kk]);
                    acc[kk] = fmaf(xv1, wv.y, acc[kk]);
                    acc[kk] = fmaf(xv2, wv.z, acc[kk]);
                }
            }
        }
    }

    // Bias add, write y, local argmax (first-index tie-break: strict >, ascending k)
    if (ow < OW_) {
        float bmax = -3.402823466e+38f;
        int bk = kg * 16;
#pragma unroll
        for (int kk = 0; kk < 16; kk++) {
            int k = kg * 16 + kk;
            float v = acc[kk] + bias[k];
            y[(((size_t)b * K_ + k) * OH_ + oh) * OW_ + ow] = v;
            if (v > bmax) { bmax = v; bk = k; }
        }
        rv[kg][ow] = bmax;
        ri[kg][ow] = bk;
    }
    __syncthreads();
    if (kg == 0 && ow < OW_) {
        float m = rv[0][ow];
        int mi = ri[0][ow];
#pragma unroll
        for (int g = 1; g < 8; g++) {
            if (rv[g][ow] > m) { m = rv[g][ow]; mi = ri[g][ow]; }
        }
        g_winners[b * NLOC + oh * OW_ + ow] = mi;
    }
}

// ---------------------------------------------------------------------------
// Kernel 3a: Hebbian partials. Grid: (K_, B_). Block: 576 threads, one per
// (c,i,j). Deterministic list build via prefix scan (no global atomics).
// ---------------------------------------------------------------------------
__global__ __launch_bounds__(576)
void hebb_partial_kernel(const float* __restrict__ x) {
    __shared__ int s_list[NLOC];
    __shared__ int s_cnt[576];

    int k = blockIdx.x;
    int b = blockIdx.y;
    int tid = threadIdx.x;

    const int* win = g_winners + b * NLOC;

    // Each thread scans strided subset (<=7 locations), records matches
    int locs[7];
    int mycnt = 0;
#pragma unroll
    for (int it = 0; it < 7; it++) {
        int loc = tid + it * 576;
        if (loc < NLOC && win[loc] == k) locs[mycnt++] = loc;
    }

    // Hillis-Steele inclusive scan over 576 counts
    int val = mycnt;
    s_cnt[tid] = val;
    __syncthreads();
    for (int off = 1; off < 576; off <<= 1) {
        int add = (tid >= off) ? s_cnt[tid - off] : 0;
        __syncthreads();
        val += add;
        s_cnt[tid] = val;
        __syncthreads();
    }
    int offset = val - mycnt;     // exclusive
    for (int m = 0; m < mycnt; m++) s_list[offset + m] = locs[m];
    __syncthreads();
    int n = s_cnt[575];

    // Gather patches: thread (c,i,j) sums x[b,c,h+i,w+j] over winning (h,w)
    int c = tid / KHW;
    int u = tid - c * KHW;
    int r = u / 3, s = u - r * 3;
    const float* xb = x + ((size_t)b * C_ + c) * H_ * W_ + r * W_ + s;

    float acc = 0.f;
    for (int idx = 0; idx < n; idx++) {
        int loc = s_list[idx];          // broadcast
        int h = loc / OW_;
        int w = loc - h * OW_;
        acc += xb[h * W_ + w];
    }
    g_part[((size_t)b * K_ + k) * WSZ + tid] = acc;
}

// ---------------------------------------------------------------------------
// Kernel 3b: reduce partials over b, scale by 1/(B*L + 1e-8)
// ---------------------------------------------------------------------------
__global__ void hebb_reduce_kernel(float* __restrict__ upd) {
    int idx = blockIdx.x * blockDim.x + threadIdx.x;
    if (idx >= (int)U_ELEMS) return;
    int k = idx / WSZ;
    int e = idx - k * WSZ;
    float s = 0.f;
    for (int b = 0; b < B_; b++) {
        s += g_part[((size_t)b * K_ + k) * WSZ + e];
    }
    // denom: float32(B*L) + 1e-8 == 123008.0f exactly in fp32
    upd[idx] = s / 123008.0f;
}

// ---------------------------------------------------------------------------
extern "C" void kernel_launch(void* const* d_in, const int* in_sizes, int n_in,
                              void* d_out, int out_size) {
    const float* x      = (const float*)d_in[0];
    const float* weight = (const float*)d_in[1];
    const float* bias   = (const float*)d_in[2];
    float* out = (float*)d_out;
    float* y   = out;
    float* upd = out + Y_ELEMS;

    cudaFuncSetAttribute(conv_argmax_kernel,
                         cudaFuncAttributeMaxDynamicSharedMemorySize,
                         CONV_SMEM_BYTES);

    norm_kernel<<<K_, 256>>>(weight);
    conv_argmax_kernel<<<dim3(B_, OH_), CONV_THREADS, CONV_SMEM_BYTES>>>(x, bias, y);
    hebb_partial_kernel<<<dim3(K_, B_), 576>>>(x);
    hebb_reduce_kernel<<<(int)((U_ELEMS + 255) / 256), 256>>>(upd);
}

// round 4
// speedup vs baseline: 1.9449x; 1.9449x over previous
#include <cuda_runtime.h>
#include <cuda_bf16.h>
#include <cstdint>
#include <math.h>

// Problem constants
#define B_   32
#define C_   64
#define H_   64
#define W_   64
#define K_   128
#define OH_  62
#define OW_  62
#define KHW  9
#define WSZ  576        // C_*KHW
#define NLOC (OH_*OW_)  // 3844
#define Y_ELEMS ((size_t)B_*K_*OH_*OW_)
#define U_ELEMS ((size_t)K_*WSZ)

#define NSTEP 36        // 9 taps * 4 c-chunks of 16

// Scratch (no cudaMalloc allowed)
__device__ int   g_winners[B_*NLOC];
__device__ float g_part[(size_t)B_*K_*WSZ];
__device__ uint4 g_w_hi_v[NSTEP*256];   // [step][k*16+cl] bf16, 2048 per step
__device__ uint4 g_w_mid_v[NSTEP*256];
__device__ uint4 g_w_lo_v[NSTEP*256];

// ---------------------------------------------------------------------------
// Kernel 1: weight norm + 3-way bf16 split into step layout.
// step = tap*4 + cc,  tap = r*3+s,  cc = c>>4,  element index k*16 + (c&15)
// ---------------------------------------------------------------------------
__global__ void norm_split_kernel(const float* __restrict__ weight) {
    __shared__ float red[256];
    __shared__ float s_nrm;
    int k = blockIdx.x;
    int tid = threadIdx.x;
    const float* wk = weight + (size_t)k * WSZ;

    float s = 0.f;
    for (int e = tid; e < WSZ; e += 256) { float v = wk[e]; s += v * v; }
    red[tid] = s;
    __syncthreads();
    for (int off = 128; off > 0; off >>= 1) {
        if (tid < off) red[tid] += red[tid + off];
        __syncthreads();
    }
    if (tid == 0) {
        float nrm = sqrtf(red[0]);
        if (nrm == 0.f) nrm = 1.f;
        s_nrm = nrm;
    }
    __syncthreads();
    float nrm = s_nrm;

    __nv_bfloat16* wh = (__nv_bfloat16*)g_w_hi_v;
    __nv_bfloat16* wm = (__nv_bfloat16*)g_w_mid_v;
    __nv_bfloat16* wl = (__nv_bfloat16*)g_w_lo_v;
    for (int e = tid; e < WSZ; e += 256) {
        int c = e / 9;
        int u = e - c * 9;            // tap
        int cc = c >> 4, cl = c & 15;
        int step = u * 4 + cc;
        float v = wk[e] / nrm;
        __nv_bfloat16 h = __float2bfloat16(v);
        float r1 = v - __bfloat162float(h);
        __nv_bfloat16 m = __float2bfloat16(r1);
        __nv_bfloat16 l = __float2bfloat16(r1 - __bfloat162float(m));
        int o = step * 2048 + k * 16 + cl;
        wh[o] = h;
        wm[o] = m;
        wl[o] = l;
    }
}

// ---------------------------------------------------------------------------
// Kernel 2: tensor-core conv + bias + argmax, 6-term bf16 split.
// Grid (OH_, B_), 256 threads = 8 warps: wm=wid&3 (channels), wn=wid>>2 (locs).
// acc += Hh*Bh + Hh*Bm + Hm*Bh + Hm*Bm + Hh*Bl + Hl*Bh   (drop <=2^-26 terms)
// ---------------------------------------------------------------------------
#define XS_W 66                      // padded w dim
#define XS_C 66                      // padded c stride
#define XS_ELEMS (3*XS_W*XS_C)       // 13068 bf16 per buffer
#define WSM_OFF 39208                // 3*XS_ELEMS=39204, padded for 16B align
#define WBUF 6144                    // per double-buffer: hi|mid|lo x 2048
#define SMEM_ELEMS (WSM_OFF + 2*WBUF)
#define DYNSMEM (SMEM_ELEMS*2)       // 102,992 bytes

#define MMA_BF16(acc, a0,a1,a2,a3, bb0,bb1) \
  asm volatile("mma.sync.aligned.m16n8k16.row.col.f32.bf16.bf16.f32 " \
    "{%0,%1,%2,%3}, {%4,%5,%6,%7}, {%8,%9}, {%0,%1,%2,%3};" \
    : "+f"(acc[0]), "+f"(acc[1]), "+f"(acc[2]), "+f"(acc[3]) \
    : "r"(a0), "r"(a1), "r"(a2), "r"(a3), "r"(bb0), "r"(bb1))

__global__ __launch_bounds__(256, 1)
void conv_tc_kernel(const float* __restrict__ x,
                    const float* __restrict__ bias,
                    float* __restrict__ y) {
    extern __shared__ __nv_bfloat16 smem[];
    __nv_bfloat16* xs_h = smem;
    __nv_bfloat16* xs_m = smem + XS_ELEMS;
    __nv_bfloat16* xs_l = smem + 2 * XS_ELEMS;
    __nv_bfloat16* wsm  = smem + WSM_OFF;   // 2 bufs x (2048 hi | 2048 mid | 2048 lo)

    __shared__ float sval[64][4];
    __shared__ int   sidx[64][4];

    int oh = blockIdx.x;
    int b  = blockIdx.y;
    int tid = threadIdx.x;
    int wid = tid >> 5, lane = tid & 31;
    int wm = wid & 3, wn = wid >> 2;
    int g = lane >> 2, t = lane & 3;

    // ---- stage x slab rows oh..oh+2, 3-way split, layout [r][w][c] ----
    const float* xb = x + (size_t)b * C_ * H_ * W_;
    for (int l = tid; l < C_ * 3 * W_; l += 256) {
        int w = l & 63;
        int cr = l >> 6;            // c*3 + r
        int c = cr / 3, r = cr - 3 * c;
        float v = xb[((size_t)c * H_ + (oh + r)) * W_ + w];
        __nv_bfloat16 h = __float2bfloat16(v);
        float r1 = v - __bfloat162float(h);
        __nv_bfloat16 m = __float2bfloat16(r1);
        __nv_bfloat16 lo = __float2bfloat16(r1 - __bfloat162float(m));
        int o = (r * XS_W + w) * XS_C + c;
        xs_h[o] = h;
        xs_m[o] = m;
        xs_l[o] = lo;
    }
    // zero pad columns w = 64, 65
    for (int l = tid; l < 3 * 2 * 64; l += 256) {
        int c = l & 63;
        int rz = l >> 6;
        int r = rz >> 1, w = 64 + (rz & 1);
        int o = (r * XS_W + w) * XS_C + c;
        __nv_bfloat16 z = __float2bfloat16(0.f);
        xs_h[o] = z; xs_m[o] = z; xs_l[o] = z;
    }
    // ---- stage weights step 0 ----
    {
        ((uint4*)(wsm))[tid]        = g_w_hi_v[tid];
        ((uint4*)(wsm + 2048))[tid] = g_w_mid_v[tid];
        ((uint4*)(wsm + 4096))[tid] = g_w_lo_v[tid];
    }
    __syncthreads();

    float acc[2][4][4];
#pragma unroll
    for (int mt = 0; mt < 2; mt++)
#pragma unroll
        for (int nt = 0; nt < 4; nt++)
#pragma unroll
            for (int q = 0; q < 4; q++) acc[mt][nt][q] = 0.f;

    const uint32_t* xh32 = (const uint32_t*)xs_h;
    const uint32_t* xm32 = (const uint32_t*)xs_m;
    const uint32_t* xl32 = (const uint32_t*)xs_l;
    int abase = (wm * 32 + g) * 8 + t;
    int wbase = wn * 32 + g;

    for (int s = 0; s < NSTEP; s++) {
        int buf = s & 1;
        if (s + 1 < NSTEP) {
            __nv_bfloat16* nb = wsm + (buf ^ 1) * WBUF;
            ((uint4*)(nb))[tid]        = g_w_hi_v[(s + 1) * 256 + tid];
            ((uint4*)(nb + 2048))[tid] = g_w_mid_v[(s + 1) * 256 + tid];
            ((uint4*)(nb + 4096))[tid] = g_w_lo_v[(s + 1) * 256 + tid];
        }
        const uint32_t* wh = (const uint32_t*)(wsm + buf * WBUF);
        const uint32_t* wmp = wh + 1024;
        const uint32_t* wl = wh + 2048;

        int tap = s >> 2, cc = s & 3;
        int r = tap / 3, sx = tap - 3 * r;

        uint32_t Ah[2][4], Am[2][4], Al[2][4];
#pragma unroll
        for (int mt = 0; mt < 2; mt++) {
            int ab = abase + mt * 128;
            Ah[mt][0] = wh[ab];       Ah[mt][1] = wh[ab + 64];
            Ah[mt][2] = wh[ab + 4];   Ah[mt][3] = wh[ab + 68];
            Am[mt][0] = wmp[ab];      Am[mt][1] = wmp[ab + 64];
            Am[mt][2] = wmp[ab + 4];  Am[mt][3] = wmp[ab + 68];
            Al[mt][0] = wl[ab];       Al[mt][1] = wl[ab + 64];
            Al[mt][2] = wl[ab + 4];   Al[mt][3] = wl[ab + 68];
        }

        int bidx0 = (r * XS_W + wbase + sx) * (XS_C / 2) + cc * 8 + t;
#pragma unroll
        for (int nt = 0; nt < 4; nt++) {
            int bi = bidx0 + nt * 8 * (XS_C / 2);
            uint32_t Bh0 = xh32[bi], Bh1 = xh32[bi + 4];
            uint32_t Bm0 = xm32[bi], Bm1 = xm32[bi + 4];
            uint32_t Bl0 = xl32[bi], Bl1 = xl32[bi + 4];
#pragma unroll
            for (int mt = 0; mt < 2; mt++) {
                MMA_BF16(acc[mt][nt], Ah[mt][0], Ah[mt][1], Ah[mt][2], Ah[mt][3], Bh0, Bh1);
                MMA_BF16(acc[mt][nt], Ah[mt][0], Ah[mt][1], Ah[mt][2], Ah[mt][3], Bm0, Bm1);
                MMA_BF16(acc[mt][nt], Am[mt][0], Am[mt][1], Am[mt][2], Am[mt][3], Bh0, Bh1);
                MMA_BF16(acc[mt][nt], Am[mt][0], Am[mt][1], Am[mt][2], Am[mt][3], Bm0, Bm1);
                MMA_BF16(acc[mt][nt], Ah[mt][0], Ah[mt][1], Ah[mt][2], Ah[mt][3], Bl0, Bl1);
                MMA_BF16(acc[mt][nt], Al[mt][0], Al[mt][1], Al[mt][2], Al[mt][3], Bh0, Bh1);
            }
        }
        __syncthreads();
    }

    // ---- epilogue: bias, y store, argmax ----
    float bb[2][2];
    bb[0][0] = bias[wm * 32 + g];
    bb[0][1] = bias[wm * 32 + g + 8];
    bb[1][0] = bias[wm * 32 + g + 16];
    bb[1][1] = bias[wm * 32 + g + 24];

    float* yb = y + (size_t)b * K_ * NLOC + oh * OW_;

#pragma unroll
    for (int nt = 0; nt < 4; nt++) {
#pragma unroll
        for (int cs = 0; cs < 2; cs++) {
            int ow = wn * 32 + nt * 8 + 2 * t + cs;
            float v = -3.402823466e+38f;
            int ki = 0;
#pragma unroll
            for (int mt = 0; mt < 2; mt++) {
#pragma unroll
                for (int rs = 0; rs < 2; rs++) {
                    int k = wm * 32 + mt * 16 + rs * 8 + g;
                    float yv = acc[mt][nt][rs * 2 + cs] + bb[mt][rs];
                    if (ow < OW_) yb[(size_t)k * NLOC + ow] = yv;
                    if (yv > v) { v = yv; ki = k; }   // ascending k -> first max
                }
            }
            // reduce over g (lane bits 2..4)
#pragma unroll
            for (int off = 4; off <= 16; off <<= 1) {
                float ov = __shfl_xor_sync(0xffffffffu, v, off);
                int ok = __shfl_xor_sync(0xffffffffu, ki, off);
                if (ov > v || (ov == v && ok < ki)) { v = ov; ki = ok; }
            }
            if (g == 0) {
                int loc = wn * 32 + nt * 8 + 2 * t + cs;
                sval[loc][wm] = v;
                sidx[loc][wm] = ki;
            }
        }
    }
    __syncthreads();
    if (tid < 64) {
        int loc = tid;
        float v = sval[loc][0];
        int ki = sidx[loc][0];
#pragma unroll
        for (int q = 1; q < 4; q++) {
            float ov = sval[loc][q];
            int ok = sidx[loc][q];
            if (ov > v) { v = ov; ki = ok; }   // ascending k across wm -> first max
        }
        if (loc < OW_) g_winners[b * NLOC + oh * OW_ + loc] = ki;
    }
}

// ---------------------------------------------------------------------------
// Kernel 3a: Hebbian partials (unchanged, known-correct).
// ---------------------------------------------------------------------------
__global__ __launch_bounds__(576)
void hebb_partial_kernel(const float* __restrict__ x) {
    __shared__ int s_list[NLOC];
    __shared__ int s_cnt[576];

    int k = blockIdx.x;
    int b = blockIdx.y;
    int tid = threadIdx.x;

    const int* win = g_winners + b * NLOC;

    int locs[7];
    int mycnt = 0;
#pragma unroll
    for (int it = 0; it < 7; it++) {
        int loc = tid + it * 576;
        if (loc < NLOC && win[loc] == k) locs[mycnt++] = loc;
    }

    int val = mycnt;
    s_cnt[tid] = val;
    __syncthreads();
    for (int off = 1; off < 576; off <<= 1) {
        int add = (tid >= off) ? s_cnt[tid - off] : 0;
        __syncthreads();
        val += add;
        s_cnt[tid] = val;
        __syncthreads();
    }
    int offset = val - mycnt;
    for (int m = 0; m < mycnt; m++) s_list[offset + m] = locs[m];
    __syncthreads();
    int n = s_cnt[575];

    int c = tid / KHW;
    int u = tid - c * KHW;
    int r = u / 3, s = u - r * 3;
    const float* xb = x + ((size_t)b * C_ + c) * H_ * W_ + r * W_ + s;

    float acc = 0.f;
    for (int idx = 0; idx < n; idx++) {
        int loc = s_list[idx];
        int h = loc / OW_;
        int w = loc - h * OW_;
        acc += xb[h * W_ + w];
    }
    g_part[((size_t)b * K_ + k) * WSZ + tid] = acc;
}

// ---------------------------------------------------------------------------
// Kernel 3b: reduce partials over b, scale.
// ---------------------------------------------------------------------------
__global__ void hebb_reduce_kernel(float* __restrict__ upd) {
    int idx = blockIdx.x * blockDim.x + threadIdx.x;
    if (idx >= (int)U_ELEMS) return;
    int k = idx / WSZ;
    int e = idx - k * WSZ;
    float s = 0.f;
    for (int bb = 0; bb < B_; bb++) {
        s += g_part[((size_t)bb * K_ + k) * WSZ + e];
    }
    upd[idx] = s / 123008.0f;   // float32(B*L)+1e-8 == 123008.0f in fp32
}

// ---------------------------------------------------------------------------
extern "C" void kernel_launch(void* const* d_in, const int* in_sizes, int n_in,
                              void* d_out, int out_size) {
    const float* x      = (const float*)d_in[0];
    const float* weight = (const float*)d_in[1];
    const float* bias   = (const float*)d_in[2];
    float* out = (float*)d_out;
    float* y   = out;
    float* upd = out + Y_ELEMS;

    cudaFuncSetAttribute(conv_tc_kernel,
                         cudaFuncAttributeMaxDynamicSharedMemorySize, DYNSMEM);

    norm_split_kernel<<<K_, 256>>>(weight);
    conv_tc_kernel<<<dim3(OH_, B_), 256, DYNSMEM>>>(x, bias, y);
    hebb_partial_kernel<<<dim3(K_, B_), 576>>>(x);
    hebb_reduce_kernel<<<(int)((U_ELEMS + 255) / 256), 256>>>(upd);
}